// round 1
// baseline (speedup 1.0000x reference)
#include <cuda_runtime.h>
#include <math.h>

#define BATCH 8
#define NNODE 2048
#define FEAT  256
#define ROWS  (BATCH * NNODE)   // 16384
#define ALPHA_LR 0.2f
#define NEG_BIG  -9.0e15f

// -------- scratch (device globals; no allocation allowed) --------
__device__ float g_Wh[(size_t)ROWS * FEAT];   // 16 MB
__device__ float g_s1[ROWS];
__device__ float g_s2[ROWS];
__device__ float g_m [ROWS];
__device__ float g_li[ROWS];                  // 1 / sum(exp)

// ================= K1: Wh = h @ W  (16384x256x256 fp32) =================
// 64x64 tile, 16-step K, 16x16 threads, 4x4 micro-tile.
__global__ __launch_bounds__(256) void k_gemm(const float* __restrict__ A,
                                              const float* __restrict__ B) {
    __shared__ float As[16][64];
    __shared__ float Bs[16][64];
    const int m0 = blockIdx.y * 64;
    const int n0 = blockIdx.x * 64;
    const int t  = threadIdx.x;
    const int ty = t >> 4, tx = t & 15;

    float acc[4][4];
#pragma unroll
    for (int i = 0; i < 4; i++)
#pragma unroll
        for (int j = 0; j < 4; j++) acc[i][j] = 0.f;

    for (int k0 = 0; k0 < 256; k0 += 16) {
        {   // A tile: 64 rows x 16 k, one float4 per thread
            int i  = t >> 2, kq = t & 3;
            float4 v = *(const float4*)&A[(size_t)(m0 + i) * 256 + k0 + kq * 4];
            As[kq * 4 + 0][i] = v.x;
            As[kq * 4 + 1][i] = v.y;
            As[kq * 4 + 2][i] = v.z;
            As[kq * 4 + 3][i] = v.w;
        }
        {   // B tile: 16 k x 64 cols, one float4 per thread
            int kk = t >> 4, j4 = t & 15;
            float4 v = *(const float4*)&B[(size_t)(k0 + kk) * 256 + n0 + j4 * 4];
            Bs[kk][j4 * 4 + 0] = v.x;
            Bs[kk][j4 * 4 + 1] = v.y;
            Bs[kk][j4 * 4 + 2] = v.z;
            Bs[kk][j4 * 4 + 3] = v.w;
        }
        __syncthreads();
#pragma unroll
        for (int kk = 0; kk < 16; kk++) {
            float a[4], b[4];
#pragma unroll
            for (int x = 0; x < 4; x++) { a[x] = As[kk][ty * 4 + x]; b[x] = Bs[kk][tx * 4 + x]; }
#pragma unroll
            for (int i = 0; i < 4; i++)
#pragma unroll
                for (int j = 0; j < 4; j++) acc[i][j] = fmaf(a[i], b[j], acc[i][j]);
        }
        __syncthreads();
    }
#pragma unroll
    for (int i = 0; i < 4; i++) {
        int row = m0 + ty * 4 + i;
#pragma unroll
        for (int j = 0; j < 4; j++)
            g_Wh[(size_t)row * 256 + n0 + tx * 4 + j] = acc[i][j];
    }
}

// ================= K2: s1/s2 row dot products =================
__global__ __launch_bounds__(256) void k_s(const float* __restrict__ a) {
    const int row = blockIdx.x;
    const int t   = threadIdx.x;
    float v  = g_Wh[(size_t)row * 256 + t];
    float p1 = v * a[t];
    float p2 = v * a[256 + t];
#pragma unroll
    for (int o = 16; o; o >>= 1) {
        p1 += __shfl_down_sync(0xffffffffu, p1, o);
        p2 += __shfl_down_sync(0xffffffffu, p2, o);
    }
    __shared__ float r1[8], r2[8];
    if ((t & 31) == 0) { r1[t >> 5] = p1; r2[t >> 5] = p2; }
    __syncthreads();
    if (t == 0) {
        float s1 = 0.f, s2 = 0.f;
#pragma unroll
        for (int w = 0; w < 8; w++) { s1 += r1[w]; s2 += r2[w]; }
        g_s1[row] = s1;
        g_s2[row] = s2;
    }
}

// ================= K3: per-row softmax stats (m, 1/l), warp per row =================
__global__ __launch_bounds__(256) void k_ml(const int* __restrict__ adj) {
    const int gwarp = (blockIdx.x * blockDim.x + threadIdx.x) >> 5;
    const int lane  = threadIdx.x & 31;
    if (gwarp >= ROWS) return;
    const int b = gwarp >> 11;   // /2048
    const float  s1   = g_s1[gwarp];
    const int*   arow = adj + (size_t)gwarp * NNODE;
    const float* s2p  = g_s2 + (size_t)b * NNODE;

    float m = -INFINITY, l = 0.f;
    for (int j = lane; j < NNODE; j += 32) {
        float x = s1 + s2p[j];
        float e = (x > 0.f) ? x : ALPHA_LR * x;
        e = (arow[j] > 0) ? e : NEG_BIG;
        if (e > m) { l = l * __expf(m - e) + 1.f; m = e; }
        else       { l += __expf(e - m); }
    }
#pragma unroll
    for (int o = 16; o; o >>= 1) {
        float m2 = __shfl_down_sync(0xffffffffu, m, o);
        float l2 = __shfl_down_sync(0xffffffffu, l, o);
        float M  = fmaxf(m, m2);
        l = l * __expf(m - M) + l2 * __expf(m2 - M);
        m = M;
    }
    if (lane == 0) { g_m[gwarp] = m; g_li[gwarp] = 1.f / l; }
}

// ================= K4: fused attention @ Wh + ELU =================
// CTA: 64 i-rows x full 256 f. Loop j in tiles of 32.
__global__ __launch_bounds__(256) void k_attn(const int* __restrict__ adj,
                                              float* __restrict__ out) {
    __shared__ float WhS[32][256];   // 32 KB
    __shared__ float pS[64][32];     // 8 KB
    __shared__ float s1S[64], mS[64], liS[64];

    const int b  = blockIdx.y;
    const int i0 = blockIdx.x * 64;
    const int t  = threadIdx.x;
    const int rowbase = b * NNODE + i0;

    if (t < 64) {
        s1S[t] = g_s1[rowbase + t];
        mS [t] = g_m [rowbase + t];
        liS[t] = g_li[rowbase + t];
    }

    float acc[64];
#pragma unroll
    for (int r = 0; r < 64; r++) acc[r] = 0.f;
    __syncthreads();

    for (int j0 = 0; j0 < NNODE; j0 += 32) {
        // stage Wh[b, j0:j0+32, :] into SMEM (float4, coalesced)
#pragma unroll
        for (int k = 0; k < 8; k++) {
            int idx4 = t + k * 256;
            int jj = idx4 >> 6, f4 = idx4 & 63;
            float4 v = *(const float4*)&g_Wh[((size_t)(b * NNODE + j0 + jj)) * 256 + f4 * 4];
            *(float4*)&WhS[jj][f4 * 4] = v;
        }
        // compute p tile (64 rows x 32 j)
#pragma unroll
        for (int k = 0; k < 8; k++) {
            int idx = t + k * 256;
            int r = idx >> 5, jj = idx & 31;
            int av = adj[((size_t)(rowbase + r)) * NNODE + j0 + jj];
            float x = s1S[r] + g_s2[b * NNODE + j0 + jj];
            float e = (x > 0.f) ? x : ALPHA_LR * x;
            e = (av > 0) ? e : NEG_BIG;
            pS[r][jj] = __expf(e - mS[r]) * liS[r];
        }
        __syncthreads();

        // acc[r] += sum_jj p[r][jj] * WhS[jj][t]
#pragma unroll 2
        for (int jj0 = 0; jj0 < 32; jj0 += 4) {
            float w0 = WhS[jj0 + 0][t];
            float w1 = WhS[jj0 + 1][t];
            float w2 = WhS[jj0 + 2][t];
            float w3 = WhS[jj0 + 3][t];
#pragma unroll
            for (int r = 0; r < 64; r++) {
                float4 pv = *(const float4*)&pS[r][jj0];
                acc[r] = fmaf(pv.x, w0,
                         fmaf(pv.y, w1,
                         fmaf(pv.z, w2,
                         fmaf(pv.w, w3, acc[r]))));
            }
        }
        __syncthreads();
    }

    // epilogue: ELU, write out
#pragma unroll
    for (int r = 0; r < 64; r++) {
        float v = acc[r];
        out[((size_t)(rowbase + r)) * 256 + t] = (v > 0.f) ? v : expm1f(v);
    }
}

// ================= launcher =================
extern "C" void kernel_launch(void* const* d_in, const int* in_sizes, int n_in,
                              void* d_out, int out_size) {
    const float* h   = (const float*)d_in[0];   // (8,2048,256) f32
    const int*   adj = (const int*)  d_in[1];   // (8,2048,2048) i32
    const float* W   = (const float*)d_in[2];   // (256,256) f32
    const float* a   = (const float*)d_in[3];   // (512,1) f32
    float* out = (float*)d_out;                 // (8,2048,256) f32

    k_gemm<<<dim3(4, 256), 256>>>(h, W);
    k_s   <<<ROWS, 256>>>(a);
    k_ml  <<<ROWS / 8, 256>>>(adj);
    k_attn<<<dim3(NNODE / 64, BATCH), 256>>>(adj, out);
}

// round 2
// speedup vs baseline: 1.7694x; 1.7694x over previous
#include <cuda_runtime.h>
#include <math.h>

#define BATCH 8
#define NNODE 2048
#define FEAT  256
#define ROWS  (BATCH * NNODE)   // 16384
#define ALPHA_LR 0.2f
#define NEG_BIG  -9.0e15f

// -------- scratch (device globals; no allocation allowed) --------
__device__ float g_Wh[(size_t)ROWS * FEAT];   // 16 MB
__device__ float g_s1[ROWS];
__device__ float g_s2[ROWS];
__device__ float g_m [ROWS];
__device__ float g_li[ROWS];                  // 1 / sum(exp)

// ---- packed fp32x2 helpers ----
__device__ __forceinline__ void fma2(unsigned long long& d,
                                     unsigned long long a,
                                     unsigned long long b) {
    asm("fma.rn.f32x2 %0, %1, %2, %0;" : "+l"(d) : "l"(a), "l"(b));
}
__device__ __forceinline__ unsigned long long dup2(float w) {
    unsigned long long r;
    asm("mov.b64 %0, {%1, %1};" : "=l"(r) : "f"(w));
    return r;
}
__device__ __forceinline__ void unpack2(unsigned long long v, float& lo, float& hi) {
    asm("mov.b64 {%0, %1}, %2;" : "=f"(lo), "=f"(hi) : "l"(v));
}

// ================= K1: Wh = h @ W  (16384x256x256 fp32) =================
__global__ __launch_bounds__(256) void k_gemm(const float* __restrict__ A,
                                              const float* __restrict__ B) {
    __shared__ float As[16][64];
    __shared__ float Bs[16][64];
    const int m0 = blockIdx.y * 64;
    const int n0 = blockIdx.x * 64;
    const int t  = threadIdx.x;
    const int ty = t >> 4, tx = t & 15;

    float acc[4][4];
#pragma unroll
    for (int i = 0; i < 4; i++)
#pragma unroll
        for (int j = 0; j < 4; j++) acc[i][j] = 0.f;

    for (int k0 = 0; k0 < 256; k0 += 16) {
        {
            int i  = t >> 2, kq = t & 3;
            float4 v = *(const float4*)&A[(size_t)(m0 + i) * 256 + k0 + kq * 4];
            As[kq * 4 + 0][i] = v.x;
            As[kq * 4 + 1][i] = v.y;
            As[kq * 4 + 2][i] = v.z;
            As[kq * 4 + 3][i] = v.w;
        }
        {
            int kk = t >> 4, j4 = t & 15;
            float4 v = *(const float4*)&B[(size_t)(k0 + kk) * 256 + n0 + j4 * 4];
            Bs[kk][j4 * 4 + 0] = v.x;
            Bs[kk][j4 * 4 + 1] = v.y;
            Bs[kk][j4 * 4 + 2] = v.z;
            Bs[kk][j4 * 4 + 3] = v.w;
        }
        __syncthreads();
#pragma unroll
        for (int kk = 0; kk < 16; kk++) {
            float a[4], b[4];
#pragma unroll
            for (int x = 0; x < 4; x++) { a[x] = As[kk][ty * 4 + x]; b[x] = Bs[kk][tx * 4 + x]; }
#pragma unroll
            for (int i = 0; i < 4; i++)
#pragma unroll
                for (int j = 0; j < 4; j++) acc[i][j] = fmaf(a[i], b[j], acc[i][j]);
        }
        __syncthreads();
    }
#pragma unroll
    for (int i = 0; i < 4; i++) {
        int row = m0 + ty * 4 + i;
#pragma unroll
        for (int j = 0; j < 4; j++)
            g_Wh[(size_t)row * 256 + n0 + tx * 4 + j] = acc[i][j];
    }
}

// ================= K2: s1/s2 row dot products =================
__global__ __launch_bounds__(256) void k_s(const float* __restrict__ a) {
    const int row = blockIdx.x;
    const int t   = threadIdx.x;
    float v  = g_Wh[(size_t)row * 256 + t];
    float p1 = v * a[t];
    float p2 = v * a[256 + t];
#pragma unroll
    for (int o = 16; o; o >>= 1) {
        p1 += __shfl_down_sync(0xffffffffu, p1, o);
        p2 += __shfl_down_sync(0xffffffffu, p2, o);
    }
    __shared__ float r1[8], r2[8];
    if ((t & 31) == 0) { r1[t >> 5] = p1; r2[t >> 5] = p2; }
    __syncthreads();
    if (t == 0) {
        float s1 = 0.f, s2 = 0.f;
#pragma unroll
        for (int w = 0; w < 8; w++) { s1 += r1[w]; s2 += r2[w]; }
        g_s1[row] = s1;
        g_s2[row] = s2;
    }
}

// ================= K3: per-row softmax stats (m, 1/l) =================
__global__ __launch_bounds__(256) void k_ml(const int* __restrict__ adj) {
    const int gwarp = (blockIdx.x * blockDim.x + threadIdx.x) >> 5;
    const int lane  = threadIdx.x & 31;
    if (gwarp >= ROWS) return;
    const int b = gwarp >> 11;
    const float  s1   = g_s1[gwarp];
    const int*   arow = adj + (size_t)gwarp * NNODE;
    const float* s2p  = g_s2 + (size_t)b * NNODE;

    float m = -INFINITY, l = 0.f;
    for (int j = lane; j < NNODE; j += 32) {
        float x = s1 + s2p[j];
        float e = (x > 0.f) ? x : ALPHA_LR * x;
        e = (arow[j] > 0) ? e : NEG_BIG;
        if (e > m) { l = l * __expf(m - e) + 1.f; m = e; }
        else       { l += __expf(e - m); }
    }
#pragma unroll
    for (int o = 16; o; o >>= 1) {
        float m2 = __shfl_down_sync(0xffffffffu, m, o);
        float l2 = __shfl_down_sync(0xffffffffu, l, o);
        float M  = fmaxf(m, m2);
        l = l * __expf(m - M) + l2 * __expf(m2 - M);
        m = M;
    }
    if (lane == 0) { g_m[gwarp] = m; g_li[gwarp] = 1.f / l; }
}

// ================= K4: fused attention @ Wh + ELU (f32x2 register GEMM) ====
// CTA tile: 128 rows x 128 feats. 256 threads, 8x8 micro-tile in split 4+4
// layout. K chunk = 16 (j dimension).
#define KJ 16
__global__ __launch_bounds__(256, 2) void k_attn(const int* __restrict__ adj,
                                                 float* __restrict__ out) {
    __shared__ float whS[KJ][128];   // 8 KB   Wh[j, f] tile
    __shared__ float pS [KJ][128];   // 8 KB   P[j, i] tile (transposed)
    __shared__ float s1S[128], mS[128], liS[128];

    const int b  = blockIdx.z;
    const int i0 = blockIdx.x * 128;
    const int fb = blockIdx.y * 128;
    const int t  = threadIdx.x;
    const int tr = t >> 4;        // 0..15
    const int tc = t & 15;        // 0..15
    const int rowbase = b * NNODE + i0;

    if (t < 128) {
        s1S[t] = g_s1[rowbase + t];
        mS [t] = g_m [rowbase + t];
        liS[t] = g_li[rowbase + t];
    }

    unsigned long long acc[4][8];
#pragma unroll
    for (int i = 0; i < 4; i++)
#pragma unroll
        for (int c = 0; c < 8; c++) acc[i][c] = 0ull;

    // staging indices
    const int w_kk = t >> 4;             // 0..15
    const int w_f0 = (t & 15) * 8;       // 0..120
    const int p_r  = t >> 1;             // 0..127
    const int p_kq = (t & 1) * 8;        // 0 or 8

    for (int j0 = 0; j0 < NNODE; j0 += KJ) {
        __syncthreads();   // prior compute done before overwrite (also orders preload)

        // ---- stage Wh tile: whS[kk][f] = Wh[b, j0+kk, fb+f]
        {
            const float* src = &g_Wh[((size_t)(b * NNODE + j0 + w_kk)) * 256 + fb + w_f0];
            float4 v0 = *(const float4*)src;
            float4 v1 = *(const float4*)(src + 4);
            *(float4*)&whS[w_kk][w_f0]     = v0;
            *(float4*)&whS[w_kk][w_f0 + 4] = v1;
        }
        // ---- stage P tile: pS[k][r] = softmax prob
        {
            const int* ar = &adj[((size_t)(rowbase + p_r)) * NNODE + j0 + p_kq];
            int4 a0 = *(const int4*)ar;
            int4 a1 = *(const int4*)(ar + 4);
            int av[8] = {a0.x, a0.y, a0.z, a0.w, a1.x, a1.y, a1.z, a1.w};
            float s1v = s1S[p_r], mv = mS[p_r], lv = liS[p_r];
            const float* s2p = &g_s2[b * NNODE + j0 + p_kq];
#pragma unroll
            for (int i = 0; i < 8; i++) {
                float x = s1v + s2p[i];
                float e = (x > 0.f) ? x : ALPHA_LR * x;
                e = (av[i] > 0) ? e : NEG_BIG;
                pS[p_kq + i][p_r] = __expf(e - mv) * lv;
            }
        }
        __syncthreads();

        // ---- compute: acc[rp][c] += p2[rp] * (w,w)[c]
#pragma unroll 4
        for (int kk = 0; kk < KJ; kk++) {
            ulonglong2 pA = *(const ulonglong2*)&pS[kk][tr * 4];       // rows tr*4..+3
            ulonglong2 pB = *(const ulonglong2*)&pS[kk][64 + tr * 4];  // rows 64+tr*4..+3
            float4 wA = *(const float4*)&whS[kk][tc * 4];              // cols tc*4..+3
            float4 wB = *(const float4*)&whS[kk][64 + tc * 4];         // cols 64+tc*4..+3
            unsigned long long w2[8];
            w2[0] = dup2(wA.x); w2[1] = dup2(wA.y);
            w2[2] = dup2(wA.z); w2[3] = dup2(wA.w);
            w2[4] = dup2(wB.x); w2[5] = dup2(wB.y);
            w2[6] = dup2(wB.z); w2[7] = dup2(wB.w);
#pragma unroll
            for (int c = 0; c < 8; c++) {
                fma2(acc[0][c], pA.x, w2[c]);
                fma2(acc[1][c], pA.y, w2[c]);
                fma2(acc[2][c], pB.x, w2[c]);
                fma2(acc[3][c], pB.y, w2[c]);
            }
        }
    }

    // ---- epilogue: unpack, ELU, store
#pragma unroll
    for (int ip = 0; ip < 4; ip++) {
        int rloc = (ip < 2) ? (tr * 4 + ip * 2) : (64 + tr * 4 + (ip - 2) * 2);
        float lo[8], hi[8];
#pragma unroll
        for (int c = 0; c < 8; c++) unpack2(acc[ip][c], lo[c], hi[c]);
#pragma unroll
        for (int h2 = 0; h2 < 2; h2++) {
            float* v = h2 ? hi : lo;
            size_t rowoff = ((size_t)(rowbase + rloc + h2)) * 256;
            float4 oA, oB;
            oA.x = (v[0] > 0.f) ? v[0] : expm1f(v[0]);
            oA.y = (v[1] > 0.f) ? v[1] : expm1f(v[1]);
            oA.z = (v[2] > 0.f) ? v[2] : expm1f(v[2]);
            oA.w = (v[3] > 0.f) ? v[3] : expm1f(v[3]);
            oB.x = (v[4] > 0.f) ? v[4] : expm1f(v[4]);
            oB.y = (v[5] > 0.f) ? v[5] : expm1f(v[5]);
            oB.z = (v[6] > 0.f) ? v[6] : expm1f(v[6]);
            oB.w = (v[7] > 0.f) ? v[7] : expm1f(v[7]);
            *(float4*)&out[rowoff + fb + tc * 4]      = oA;
            *(float4*)&out[rowoff + fb + 64 + tc * 4] = oB;
        }
    }
}

// ================= launcher =================
extern "C" void kernel_launch(void* const* d_in, const int* in_sizes, int n_in,
                              void* d_out, int out_size) {
    const float* h   = (const float*)d_in[0];   // (8,2048,256) f32
    const int*   adj = (const int*)  d_in[1];   // (8,2048,2048) i32
    const float* W   = (const float*)d_in[2];   // (256,256) f32
    const float* a   = (const float*)d_in[3];   // (512,1) f32
    float* out = (float*)d_out;                 // (8,2048,256) f32

    k_gemm<<<dim3(4, 256), 256>>>(h, W);
    k_s   <<<ROWS, 256>>>(a);
    k_ml  <<<ROWS / 8, 256>>>(adj);
    k_attn<<<dim3(NNODE / 128, 2, BATCH), 256>>>(adj, out);
}